// round 8
// baseline (speedup 1.0000x reference)
#include <cuda_runtime.h>
#include <cuda_bf16.h>
#include <cstdint>

#define B_DIM 8
#define L_DIM 4096
#define D_DIM 1024
#define N_DIM 128
#define M_TOTAL (B_DIM * L_DIM)   // 32768
#define CHUNK 64
#define NCHUNK (L_DIM / CHUNK)    // 64
#define TOT_CHUNKS (B_DIM * NCHUNK) // 512

// Scratch (no cudaMalloc allowed)
__device__ float g_xproj[(size_t)M_TOTAL * N_DIM];
__device__ float g_carry[TOT_CHUNKS * N_DIM];
__device__ float g_prefix[TOT_CHUNKS * N_DIM];
__device__ __nv_bfloat16 g_hsh[(size_t)M_TOTAL * N_DIM];
__device__ __nv_bfloat16 g_hsl[(size_t)M_TOTAL * N_DIM];
__device__ __nv_bfloat16 g_Bwh[N_DIM * D_DIM];
__device__ __nv_bfloat16 g_Bwl[N_DIM * D_DIM];
__device__ __nv_bfloat16 g_Cwh[D_DIM * N_DIM];
__device__ __nv_bfloat16 g_Cwl[D_DIM * N_DIM];

typedef unsigned long long u64;
typedef uint32_t u32;

__device__ __forceinline__ u32 smem_to_u32(const void* p) {
    u32 a;
    asm("{ .reg .u64 t; cvta.to.shared.u64 t, %1; cvt.u32.u64 %0, t; }"
        : "=r"(a) : "l"(p));
    return a;
}
__device__ __forceinline__ u32 swz(u32 o) { return o ^ ((o >> 3) & 0x70); }

__device__ __forceinline__ void ldsm4(u32* r, u32 addr) {
    asm volatile("ldmatrix.sync.aligned.m8n8.x4.shared.b16 {%0,%1,%2,%3}, [%4];"
                 : "=r"(r[0]), "=r"(r[1]), "=r"(r[2]), "=r"(r[3]) : "r"(addr));
}
__device__ __forceinline__ void mma16816(float* c, const u32* a, const u32* b) {
    asm volatile("mma.sync.aligned.m16n8k16.row.col.f32.bf16.bf16.f32 "
                 "{%0,%1,%2,%3}, {%4,%5,%6,%7}, {%8,%9}, {%0,%1,%2,%3};"
                 : "+f"(c[0]), "+f"(c[1]), "+f"(c[2]), "+f"(c[3])
                 : "r"(a[0]), "r"(a[1]), "r"(a[2]), "r"(a[3]),
                   "r"(b[0]), "r"(b[1]));
}
__device__ __forceinline__ u64 pack_bf16x4(float a, float b, float c, float d) {
    __nv_bfloat162 p0 = __floats2bfloat162_rn(a, b);
    __nv_bfloat162 p1 = __floats2bfloat162_rn(c, d);
    u32 lo = *(u32*)&p0, hi = *(u32*)&p1;
    return ((u64)hi << 32) | lo;
}
#define CP_ASYNC16(dst, src) \
    asm volatile("cp.async.cg.shared.global [%0], [%1], 16;" :: "r"(dst), "l"(src))
#define CP_COMMIT() asm volatile("cp.async.commit_group;")
#define CP_WAIT0() asm volatile("cp.async.wait_group 0;")
#define CP_WAIT1() asm volatile("cp.async.wait_group 1;")

// ───────── GEMM1: xproj = x @ B_w^T ─────────
// A (x) fp32 staged via cp.async (raw, padded rows), converted by the SAME
// thread that copied it (no wait→convert barrier). B presplit bf16 cp.async.
// CTA 128x128, warp tile 64x32, KC=32 fp32, 2 stages, 1 barrier per chunk.
// Stage layout: bfA @0 (16KB), bfB @16384 (16KB), rawA @32768 (128x144B).
__global__ void __launch_bounds__(256, 2)
gemm1_hmma(const float* __restrict__ A,
           const __nv_bfloat16* __restrict__ Bwh, const __nv_bfloat16* __restrict__ Bwl,
           float* __restrict__ C)
{
    constexpr int KTOT = D_DIM;
    constexpr int KC = 32;
    constexpr int NC = KTOT / KC;      // 32
    constexpr int STG = 51200;         // 50KB per stage (mult of 1024)
    constexpr int RAWS = 144;          // padded raw row stride (bank-safe)

    extern __shared__ char dsm[];
    const u32 raw = smem_to_u32(dsm);
    const u32 base = (raw + 1023u) & ~1023u;
    char* dbase = dsm + (base - raw);

    const int tid  = threadIdx.x;
    const int lane = tid & 31;
    const int warp = tid >> 5;
    const int wr = warp & 1;
    const int wc = warp >> 1;
    const long row0 = (long)blockIdx.y * 128;

    const int r  = tid >> 1;
    const int hv = tid & 1;
    const int cf0 = hv * 16;
    const float* Arow = A + (row0 + r) * (long)KTOT;
    const __nv_bfloat16* Bsrc = (hv ? Bwl : Bwh) + (size_t)r * KTOT;

    const int g  = lane >> 3;
    const int ln = lane & 7;
    const int rA = wr * 64 + (g & 1) * 8 + ln;
    const int cA = (g >> 1) * 16;
    const int rB = wc * 32 + (g >> 1) * 8 + ln;
    const int cB = (g & 1) * 16;

    float acc[4][4][4];
#pragma unroll
    for (int i = 0; i < 4; i++)
#pragma unroll
        for (int j = 0; j < 4; j++)
#pragma unroll
            for (int q = 0; q < 4; q++) acc[i][j][q] = 0.0f;

    auto issue_rawA = [&](int c) {
        const u32 dst = base + (c & 1) * STG + 32768 + (u32)r * RAWS + hv * 64;
        const float* src = Arow + c * KC + cf0;
#pragma unroll
        for (int i = 0; i < 4; i++)
            CP_ASYNC16(dst + i * 16, src + i * 4);
        CP_COMMIT();
    };
    auto issue_B = [&](int c) {
        const u32 dst = base + (c & 1) * STG + 16384;
        const __nv_bfloat16* src = Bsrc + c * KC;
#pragma unroll
        for (int i = 0; i < 4; i++)
            CP_ASYNC16(dst + swz((u32)r * 128 + hv * 64 + i * 16), src + i * 8);
        CP_COMMIT();
    };

    // prologue: chunk 0 (rawA + B in one group)
    {
        const u32 dst = base + 32768 + (u32)r * RAWS + hv * 64;
        const float* src = Arow + cf0;
#pragma unroll
        for (int i = 0; i < 4; i++)
            CP_ASYNC16(dst + i * 16, src + i * 4);
        const u32 bdst = base + 16384;
#pragma unroll
        for (int i = 0; i < 4; i++)
            CP_ASYNC16(bdst + swz((u32)r * 128 + hv * 64 + i * 16), Bsrc + i * 8);
        CP_COMMIT();
    }

    for (int c = 0; c < NC; c++) {
        const int s = c & 1;
        char* stg = dbase + s * STG;

        if (c + 1 < NC) { issue_rawA(c + 1); CP_WAIT1(); }
        else            { CP_WAIT0(); }

        // convert own raw fp32 -> bf16 hi/lo (no barrier needed before this)
        {
            char* rawp = stg + 32768 + r * RAWS + hv * 64;
            char* bfA  = stg;
#pragma unroll
            for (int q = 0; q < 4; q++) {
                float4 v = *(float4*)(rawp + q * 16);
                float hx = __bfloat162float(__float2bfloat16(v.x));
                float hy = __bfloat162float(__float2bfloat16(v.y));
                float hz = __bfloat162float(__float2bfloat16(v.z));
                float hw = __bfloat162float(__float2bfloat16(v.w));
                const u32 cbyte = (u32)(cf0 + q * 4) * 2;
                *(u64*)(bfA + swz((u32)r * 128 + cbyte))      = pack_bf16x4(hx, hy, hz, hw);
                *(u64*)(bfA + swz((u32)r * 128 + 64 + cbyte)) =
                    pack_bf16x4(v.x - hx, v.y - hy, v.z - hz, v.w - hw);
            }
        }
        __syncthreads();   // bfA/bfB of stage s visible; MMA(c-1) finished everywhere
        if (c + 1 < NC) issue_B(c + 1);   // safe: into other stage, after sync

        const u32 ab = base + s * STG;
        const u32 bb = ab + 16384;
#pragma unroll
        for (int ks = 0; ks < 2; ks++) {
            const u32 kA = (u32)(ks * 32 + cA);
            const u32 kB = (u32)(ks * 32 + cB);
            u32 ah[4][4], al[4][4], bf[2][4];
#pragma unroll
            for (int mt = 0; mt < 4; mt++)
                ldsm4(ah[mt], ab + swz((u32)(rA + mt * 16) * 128 + kA));
#pragma unroll
            for (int p = 0; p < 2; p++)
                ldsm4(bf[p], bb + swz((u32)(rB + p * 16) * 128 + kB));
#pragma unroll
            for (int mt = 0; mt < 4; mt++)
#pragma unroll
                for (int nt = 0; nt < 4; nt++)
                    mma16816(acc[mt][nt], ah[mt], &bf[nt >> 1][(nt & 1) * 2]);
#pragma unroll
            for (int mt = 0; mt < 4; mt++)
                ldsm4(al[mt], ab + swz((u32)(rA + mt * 16) * 128 + 64 + kA));
#pragma unroll
            for (int mt = 0; mt < 4; mt++)
#pragma unroll
                for (int nt = 0; nt < 4; nt++)
                    mma16816(acc[mt][nt], al[mt], &bf[nt >> 1][(nt & 1) * 2]);
#pragma unroll
            for (int p = 0; p < 2; p++)
                ldsm4(bf[p], bb + swz((u32)(rB + p * 16) * 128 + 64 + kB));
#pragma unroll
            for (int mt = 0; mt < 4; mt++)
#pragma unroll
                for (int nt = 0; nt < 4; nt++)
                    mma16816(acc[mt][nt], ah[mt], &bf[nt >> 1][(nt & 1) * 2]);
        }
        // no end barrier: next iter's convert targets the other stage, and its
        // pre-MMA barrier orders stage reuse.
        __syncthreads();
    }

    const int er = lane >> 2;
    const int ec = (lane & 3) * 2;
#pragma unroll
    for (int mt = 0; mt < 4; mt++)
#pragma unroll
        for (int nt = 0; nt < 4; nt++) {
            const long m = row0 + wr * 64 + mt * 16 + er;
            const long n = wc * 32 + nt * 8 + ec;
            *(float2*)(C + m * (long)N_DIM + n) = make_float2(acc[mt][nt][0], acc[mt][nt][1]);
            *(float2*)(C + (m + 8) * (long)N_DIM + n) = make_float2(acc[mt][nt][2], acc[mt][nt][3]);
        }
}

// ───────── GEMM2: y = hs @ C_w^T + x*Dp. All bf16 presplit, 3-stage, 1 barrier/chunk ─────
__global__ void __launch_bounds__(256, 2)
gemm2_hmma(const __nv_bfloat16* __restrict__ hsh, const __nv_bfloat16* __restrict__ hsl,
           const __nv_bfloat16* __restrict__ Cwh, const __nv_bfloat16* __restrict__ Cwl,
           float* __restrict__ C,
           const float* __restrict__ X, const float* __restrict__ Dp)
{
    constexpr int NVC = 6;
    constexpr int STAGE = 32768;

    extern __shared__ char dsm[];
    const u32 raw = smem_to_u32(dsm);
    const u32 base = (raw + 1023u) & ~1023u;

    const int tid  = threadIdx.x;
    const int lane = tid & 31;
    const int warp = tid >> 5;
    const int wr = warp & 1;
    const int wc = warp >> 1;
    const long row0 = (long)blockIdx.y * 128;
    const long col0 = (long)blockIdx.x * 128;

    const int r2 = tid >> 1;
    const int hv = tid & 1;

    const int g  = lane >> 3;
    const int ln = lane & 7;
    const int rA = wr * 64 + (g & 1) * 8 + ln;
    const int cA = (g >> 1) * 16;
    const int rB = wc * 32 + (g >> 1) * 8 + ln;
    const int cB = (g & 1) * 16;

    float acc[4][4][4];
#pragma unroll
    for (int i = 0; i < 4; i++)
#pragma unroll
        for (int j = 0; j < 4; j++)
#pragma unroll
            for (int q = 0; q < 4; q++) acc[i][j][q] = 0.0f;

    auto issue = [&](int vc) {
        const u32 sb = base + (vc % 3) * STAGE;
        const int t  = vc >> 1;
        const int kk = (vc & 1) * 64;
        const __nv_bfloat16* As = (t == 1) ? hsl : hsh;
        const __nv_bfloat16* Bs = (t == 2) ? Cwl : Cwh;
        const __nv_bfloat16* asrc = As + (row0 + r2) * (long)N_DIM + kk + hv * 32;
        const __nv_bfloat16* bsrc = Bs + (col0 + r2) * (long)N_DIM + kk + hv * 32;
#pragma unroll
        for (int i = 0; i < 4; i++)
            CP_ASYNC16(sb + swz((u32)r2 * 128 + hv * 64 + i * 16), asrc + i * 8);
#pragma unroll
        for (int i = 0; i < 4; i++)
            CP_ASYNC16(sb + 16384 + swz((u32)r2 * 128 + hv * 64 + i * 16), bsrc + i * 8);
        CP_COMMIT();
    };

    issue(0);
    issue(1);

    for (int vc = 0; vc < NVC; vc++) {
        if (vc + 1 < NVC) { CP_WAIT1(); } else { CP_WAIT0(); }
        __syncthreads();                  // stage vc data visible; MMA(vc-1) done
        if (vc + 2 < NVC) issue(vc + 2);  // into stage (vc-1)%3, safe after sync

        const u32 ab = base + (vc % 3) * STAGE;
        const u32 bb = ab + 16384;
#pragma unroll
        for (int ks = 0; ks < 4; ks++) {
            const u32 kA = (u32)(ks * 32 + cA);
            const u32 kB = (u32)(ks * 32 + cB);
            u32 ah[4][4], bf[2][4];
#pragma unroll
            for (int mt = 0; mt < 4; mt++)
                ldsm4(ah[mt], ab + swz((u32)(rA + mt * 16) * 128 + kA));
#pragma unroll
            for (int p = 0; p < 2; p++)
                ldsm4(bf[p], bb + swz((u32)(rB + p * 16) * 128 + kB));
#pragma unroll
            for (int mt = 0; mt < 4; mt++)
#pragma unroll
                for (int nt = 0; nt < 4; nt++)
                    mma16816(acc[mt][nt], ah[mt], &bf[nt >> 1][(nt & 1) * 2]);
        }
    }

    const int er = lane >> 2;
    const int ec = (lane & 3) * 2;
#pragma unroll
    for (int mt = 0; mt < 4; mt++)
#pragma unroll
        for (int nt = 0; nt < 4; nt++) {
            const long m = row0 + wr * 64 + mt * 16 + er;
            const long n = col0 + wc * 32 + nt * 8 + ec;
            float2 dv = *(const float2*)(Dp + n);
            float2 x0 = *(const float2*)(X + m * (long)D_DIM + n);
            float2 x1 = *(const float2*)(X + (m + 8) * (long)D_DIM + n);
            float2 o0, o1;
            o0.x = fmaf(x0.x, dv.x, acc[mt][nt][0]);
            o0.y = fmaf(x0.y, dv.y, acc[mt][nt][1]);
            o1.x = fmaf(x1.x, dv.x, acc[mt][nt][2]);
            o1.y = fmaf(x1.y, dv.y, acc[mt][nt][3]);
            *(float2*)(C + m * (long)D_DIM + n) = o0;
            *(float2*)(C + (m + 8) * (long)D_DIM + n) = o1;
        }
}

// ───────── weight presplit ─────────
__global__ void split2_kernel(const float* __restrict__ src,
                              __nv_bfloat16* __restrict__ dh,
                              __nv_bfloat16* __restrict__ dl, int n)
{
    int i = blockIdx.x * blockDim.x + threadIdx.x;
    if (i < n) {
        float v = src[i];
        __nv_bfloat16 h = __float2bfloat16(v);
        dh[i] = h;
        dl[i] = __float2bfloat16(v - __bfloat162float(h));
    }
}

// ───────── scan: 3 passes, CHUNK=64 ─────────
__global__ void __launch_bounds__(128)
scan_carry(const float* __restrict__ xproj, float* __restrict__ carry,
           const float* __restrict__ log_A)
{
    int n = threadIdx.x;
    int chunk = blockIdx.x;
    int b = blockIdx.y;
    float A = expf(log_A[n]);
    const float* src = xproj + ((size_t)b * L_DIM + (size_t)chunk * CHUNK) * N_DIM + n;
    float h = 0.0f;
#pragma unroll 8
    for (int i = 0; i < CHUNK; i++)
        h = fmaf(A, h, src[(size_t)i * N_DIM]);
    carry[(b * NCHUNK + chunk) * N_DIM + n] = h;
}

__global__ void __launch_bounds__(128)
carry_scan(const float* __restrict__ carry, float* __restrict__ prefix,
           const float* __restrict__ log_A)
{
    int n = threadIdx.x;
    int b = blockIdx.x;
    float Ac = expf((float)CHUNK * log_A[n]);
    float h = 0.0f;
#pragma unroll
    for (int c = 0; c < NCHUNK; c++) {
        prefix[(b * NCHUNK + c) * N_DIM + n] = h;   // exclusive
        h = fmaf(Ac, h, carry[(b * NCHUNK + c) * N_DIM + n]);
    }
}

__global__ void __launch_bounds__(128)
scan_split(const float* __restrict__ xproj, const float* __restrict__ prefix,
           __nv_bfloat16* __restrict__ hsh, __nv_bfloat16* __restrict__ hsl,
           const float* __restrict__ log_A)
{
    int n = threadIdx.x;
    int chunk = blockIdx.x;
    int b = blockIdx.y;
    float A = expf(log_A[n]);
    size_t bo = ((size_t)b * L_DIM + (size_t)chunk * CHUNK) * N_DIM + n;
    const float* src = xproj + bo;
    float h = prefix[(b * NCHUNK + chunk) * N_DIM + n];
#pragma unroll 8
    for (int i = 0; i < CHUNK; i++) {
        h = fmaf(A, h, src[(size_t)i * N_DIM]);
        __nv_bfloat16 hb = __float2bfloat16(h);
        hsh[bo + (size_t)i * N_DIM] = hb;
        hsl[bo + (size_t)i * N_DIM] = __float2bfloat16(h - __bfloat162float(hb));
    }
}

__global__ void final_state_kernel(const float* __restrict__ xproj,
                                   float* __restrict__ fs)
{
    int n = threadIdx.x;
    float s = 0.0f;
#pragma unroll
    for (int b = 0; b < B_DIM; b++)
        s += xproj[((size_t)b * L_DIM + (L_DIM - 1)) * N_DIM + n];
    s *= (1.0f / B_DIM);
#pragma unroll
    for (int b = 0; b < B_DIM; b++)
        fs[b * N_DIM + n] = s;
}

// ─────────────────────────────── launch ───────────────────────────────
extern "C" void kernel_launch(void* const* d_in, const int* in_sizes, int n_in,
                              void* d_out, int out_size)
{
    const float* x       = (const float*)d_in[0];
    const float* B_w     = (const float*)d_in[1];
    const float* C_w     = (const float*)d_in[2];
    const float* log_A   = (const float*)d_in[3];
    const float* D_param = (const float*)d_in[4];

    float* y  = (float*)d_out;
    float* fs = y + ((size_t)out_size - (size_t)B_DIM * N_DIM);

    float *xproj, *carry, *prefix;
    __nv_bfloat16 *hsh, *hsl, *Bwh, *Bwl, *Cwh, *Cwl;
    cudaGetSymbolAddress((void**)&xproj, g_xproj);
    cudaGetSymbolAddress((void**)&carry, g_carry);
    cudaGetSymbolAddress((void**)&prefix, g_prefix);
    cudaGetSymbolAddress((void**)&hsh, g_hsh);
    cudaGetSymbolAddress((void**)&hsl, g_hsl);
    cudaGetSymbolAddress((void**)&Bwh, g_Bwh);
    cudaGetSymbolAddress((void**)&Bwl, g_Bwl);
    cudaGetSymbolAddress((void**)&Cwh, g_Cwh);
    cudaGetSymbolAddress((void**)&Cwl, g_Cwl);

    const int SMEM1 = 2 * 51200 + 1024;   // 103424
    const int SMEM2 = 3 * 32768 + 1024;   // 99328
    cudaFuncSetAttribute(gemm1_hmma, cudaFuncAttributeMaxDynamicSharedMemorySize, SMEM1);
    cudaFuncSetAttribute(gemm2_hmma, cudaFuncAttributeMaxDynamicSharedMemorySize, SMEM2);

    split2_kernel<<<(N_DIM * D_DIM + 255) / 256, 256>>>(B_w, Bwh, Bwl, N_DIM * D_DIM);
    split2_kernel<<<(D_DIM * N_DIM + 255) / 256, 256>>>(C_w, Cwh, Cwl, D_DIM * N_DIM);

    // GEMM1: xproj = x @ B_w^T
    {
        dim3 grid(1, M_TOTAL / 128);
        gemm1_hmma<<<grid, 256, SMEM1>>>(x, Bwh, Bwl, xproj);
    }

    // scan: carries -> prefix -> fixed split hs
    {
        dim3 grid(NCHUNK, B_DIM);
        scan_carry<<<grid, 128>>>(xproj, carry, log_A);
        carry_scan<<<B_DIM, 128>>>(carry, prefix, log_A);
        scan_split<<<grid, 128>>>(xproj, prefix, hsh, hsl, log_A);
    }

    // GEMM2: y = hs @ C_w^T + x * D_param
    {
        dim3 grid(D_DIM / 128, M_TOTAL / 128);
        gemm2_hmma<<<grid, 256, SMEM2>>>(hsh, hsl, Cwh, Cwl, y, x, D_param);
    }

    final_state_kernel<<<1, N_DIM>>>(xproj, fs);
}